// round 11
// baseline (speedup 1.0000x reference)
#include <cuda_runtime.h>

#define T_DEPTH 200000
#define V_DIM   130
#define H_DIM   512

// Output layout (floats): ot | Val | stg | rt | h_new | c_new
#define OUT_OT  0
#define OUT_VAL 512
#define OUT_STG 26000642   // 512 + 200001*130
#define OUT_RT  26200643
#define OUT_H   26200773
#define OUT_C   26201797

#define NCHAIN   64
#define NCOPY    528
#define GRID_SZ  (NCHAIN + NCOPY)   // 592 = 148 SMs * 4 blocks
#define NTHREADS 256
#define VAL_F4   6500000            // 200000*130/4

// Block-granular work stealing: chunks of 2048 float4 (32 KB).
#define CHUNK_F4   2048
#define NCHUNKS    3174             // 3173 full + 1 partial (1696 f4)
#define NPARTS     (GRID_SZ - 1)
#define TICKETS    (NCHUNKS + NPARTS)

#define NT_COPY  (NCOPY * NTHREADS)

__device__ __align__(16) float g_h1[H_DIM];
__device__ __align__(16) float g_h2[H_DIM];
__device__ __align__(16) float g_vt[V_DIM + 2];
__device__ float g_dt, g_ut;

// Monotonic (never reset) counters — safe across graph replays.
__device__ unsigned int g_entry;
__device__ unsigned int g_c1, g_c2, g_c3, g_cstg;
__device__ unsigned int g_work;

__device__ __forceinline__ void spin_geq(unsigned int* p, unsigned int tgt) {
    volatile unsigned int* vp = (volatile unsigned int*)p;
    while (*vp < tgt) __nanosleep(64);
}

__device__ __forceinline__ void l2_prefetch(const void* p) {
    asm volatile("prefetch.global.L2 [%0];" :: "l"(p));
}

// L2 policies: src stays resident across graph replays (read-only, identical
// every run); dst streams out (must be written back regardless).
__device__ __forceinline__ unsigned long long pol_keep() {
    unsigned long long p;
    asm("createpolicy.fractional.L2::evict_last.b64 %0, 1.0;" : "=l"(p));
    return p;
}
__device__ __forceinline__ unsigned long long pol_stream() {
    unsigned long long p;
    asm("createpolicy.fractional.L2::evict_first.b64 %0, 1.0;" : "=l"(p));
    return p;
}
__device__ __forceinline__ float4 ld_keep(const float4* p, unsigned long long pol) {
    float4 v;
    asm volatile("ld.global.nc.L2::cache_hint.v4.f32 {%0,%1,%2,%3}, [%4], %5;"
                 : "=f"(v.x), "=f"(v.y), "=f"(v.z), "=f"(v.w)
                 : "l"(p), "l"(pol));
    return v;
}
__device__ __forceinline__ void st_stream(float4* p, float4 v, unsigned long long pol) {
    asm volatile("st.global.L2::cache_hint.v4.f32 [%0], {%1,%2,%3,%4}, %5;"
                 :: "l"(p), "f"(v.x), "f"(v.y), "f"(v.z), "f"(v.w), "l"(pol)
                 : "memory");
}

__device__ __forceinline__ float warp_sum(float v) {
#pragma unroll
    for (int o = 16; o; o >>= 1) v += __shfl_xor_sync(0xffffffffu, v, o);
    return v;
}
__device__ __forceinline__ float sigm(float x) { return 1.0f / (1.0f + expf(-x)); }

// Block-granular stealing copy over [0, VAL_F4) float4.
// Grabs per block per run == chunks_done + 1 (deterministic; total == TICKETS).
__device__ __forceinline__ void val_copy_steal(
    const float4* __restrict__ src, float4* __restrict__ dst,
    unsigned int run, unsigned int* s_chunk)
{
    const unsigned long long pk = pol_keep();
    const unsigned long long ps = pol_stream();
    const unsigned int base = run * (unsigned int)TICKETS;
    for (;;) {
        if (threadIdx.x == 0) *s_chunk = atomicAdd(&g_work, 1u) - base;
        __syncthreads();
        unsigned int chunk = *s_chunk;
        __syncthreads();            // s_chunk free for next grab
        if (chunk >= NCHUNKS) break;
        int b = chunk * CHUNK_F4;
        if (chunk != NCHUNKS - 1) {
            int i = b + threadIdx.x;
            float4 v0 = ld_keep(src + i, pk);
            float4 v1 = ld_keep(src + i + 256, pk);
            float4 v2 = ld_keep(src + i + 512, pk);
            float4 v3 = ld_keep(src + i + 768, pk);
            float4 v4 = ld_keep(src + i + 1024, pk);
            float4 v5 = ld_keep(src + i + 1280, pk);
            float4 v6 = ld_keep(src + i + 1536, pk);
            float4 v7 = ld_keep(src + i + 1792, pk);
            st_stream(dst + i, v0, ps);
            st_stream(dst + i + 256, v1, ps);
            st_stream(dst + i + 512, v2, ps);
            st_stream(dst + i + 768, v3, ps);
            st_stream(dst + i + 1024, v4, ps);
            st_stream(dst + i + 1280, v5, ps);
            st_stream(dst + i + 1536, v6, ps);
            st_stream(dst + i + 1792, v7, ps);
        } else {
            for (int j = b + threadIdx.x; j < VAL_F4; j += NTHREADS)
                st_stream(dst + j, ld_keep(src + j, pk), ps);
        }
    }
}

// One warp computes one hidden unit j (all 4 gates) of an LSTM cell.
__device__ __forceinline__ void lstm_cell_warp(
    int j, int lane,
    const float* __restrict__ Wih, const float* __restrict__ Whh,
    const float* __restrict__ bih, const float* __restrict__ bhh,
    const float* __restrict__ x, const float* __restrict__ x2, int in_dim,
    const float* __restrict__ h, const float* __restrict__ c,
    float* __restrict__ hg,
    float* __restrict__ ho, float* __restrict__ co)
{
    float gate[4];
#pragma unroll
    for (int g = 0; g < 4; ++g) {
        int row = g * H_DIM + j;
        const float* wi = Wih + (size_t)row * in_dim;
        float acc = 0.0f;
        for (int k = lane; k < in_dim; k += 32) {
            float xv = x[k];
            if (x2) xv += x2[k];
            acc = fmaf(wi[k], xv, acc);
        }
        const float4* wh4 = reinterpret_cast<const float4*>(Whh + (size_t)row * H_DIM);
        const float4* h4  = reinterpret_cast<const float4*>(h);
#pragma unroll
        for (int m = 0; m < 4; ++m) {
            float4 a = wh4[lane + 32 * m];
            float4 b = h4[lane + 32 * m];
            acc = fmaf(a.x, b.x, acc);
            acc = fmaf(a.y, b.y, acc);
            acc = fmaf(a.z, b.z, acc);
            acc = fmaf(a.w, b.w, acc);
        }
        acc = warp_sum(acc);
        gate[g] = acc + bih[row] + bhh[row];
    }
    if (lane == 0) {
        float ig = sigm(gate[0]);
        float fg = sigm(gate[1]);
        float gg = tanhf(gate[2]);
        float og = sigm(gate[3]);
        float cn = fg * c[j] + ig * gg;
        float hn = og * tanhf(cn);
        hg[j] = hn;              // device-global for next stage
        ho[j] = hn; co[j] = cn;  // output buffer
    }
}

__global__ __launch_bounds__(NTHREADS, 4) void fused_controller(
    const float* __restrict__ input, const float* __restrict__ prev_Val,
    const float* __restrict__ prev_stg, const float* __restrict__ prev_read,
    const float* __restrict__ prev_h, const float* __restrict__ prev_c,
    const float* __restrict__ Wih0, const float* __restrict__ Whh0,
    const float* __restrict__ bih0, const float* __restrict__ bhh0,
    const float* __restrict__ Wih1, const float* __restrict__ Whh1,
    const float* __restrict__ bih1, const float* __restrict__ bhh1,
    const float* __restrict__ Wd, const float* __restrict__ Bd,
    const float* __restrict__ Wu, const float* __restrict__ Bu,
    const float* __restrict__ Wv, const float* __restrict__ Bv,
    const float* __restrict__ Wo, const float* __restrict__ Bo,
    float* __restrict__ out)
{
    __shared__ unsigned int s_run, s_chunk;
    if (threadIdx.x == 0) {
        unsigned int t = atomicAdd(&g_entry, 1u);
        s_run = t / GRID_SZ;   // all blocks of one launch agree
    }
    __syncthreads();
    const unsigned int run = s_run;

    const float4* vsrc = reinterpret_cast<const float4*>(prev_Val);
    float4* vdst = reinterpret_cast<float4*>(out + OUT_VAL);
    const int warp = threadIdx.x >> 5;
    const int lane = threadIdx.x & 31;

    // ---------------- COPY ROLE (blocks NCHAIN..) ----------------
    if (blockIdx.x >= NCHAIN) {
        const int tid = (blockIdx.x - NCHAIN) * NTHREADS + threadIdx.x;

        // L2 prefetch of weights used by the chain (128B lines).
        {
            const char* p;
            p = (const char*)Wih0; for (int l = tid; l < 8320;  l += NT_COPY) l2_prefetch(p + (size_t)l * 128);
            p = (const char*)Whh0; for (int l = tid; l < 32768; l += NT_COPY) l2_prefetch(p + (size_t)l * 128);
            p = (const char*)Wih1; for (int l = tid; l < 32768; l += NT_COPY) l2_prefetch(p + (size_t)l * 128);
            p = (const char*)Whh1; for (int l = tid; l < 32768; l += NT_COPY) l2_prefetch(p + (size_t)l * 128);
            p = (const char*)Wo;   for (int l = tid; l < 8192;  l += NT_COPY) l2_prefetch(p + (size_t)l * 128);
            p = (const char*)Wv;   for (int l = tid; l < 2080;  l += NT_COPY) l2_prefetch(p + (size_t)l * 128);
        }

        // stg bulk: stg[i] = max(0, prev_stg[i]); the scan overwrites the
        // popped prefix later (ordered via g_cstg).
        const float2* s2 = reinterpret_cast<const float2*>(prev_stg);
        float2* d2 = reinterpret_cast<float2*>(out + OUT_STG);
        for (int i = tid; i < T_DEPTH / 2; i += NT_COPY) {
            float2 v = s2[i];
            v.x = fmaxf(v.x, 0.0f);
            v.y = fmaxf(v.y, 0.0f);
            d2[i] = v;
        }
        __threadfence();
        __syncthreads();
        if (threadIdx.x == 0) atomicAdd(&g_cstg, 1u);

        val_copy_steal(vsrc, vdst, run, &s_chunk);
        return;
    }

    // ---------------- CHAIN ROLE (blocks 0..63) ----------------

    // cell0: 8 warps/block x 64 blocks = 512 units
    {
        int j = blockIdx.x * 8 + warp;
        lstm_cell_warp(j, lane, Wih0, Whh0, bih0, bhh0,
                       input, prev_read, V_DIM,
                       prev_h, prev_c,
                       g_h1, out + OUT_H, out + OUT_C);
    }
    __threadfence();
    __syncthreads();
    if (threadIdx.x == 0) {
        atomicAdd(&g_c1, 1u);
        spin_geq(&g_c1, (run + 1) * NCHAIN);
    }
    __syncthreads();
    __threadfence();

    // cell1
    {
        int j = blockIdx.x * 8 + warp;
        lstm_cell_warp(j, lane, Wih1, Whh1, bih1, bhh1,
                       g_h1, nullptr, H_DIM,
                       prev_h + H_DIM, prev_c + H_DIM,
                       g_h2, out + OUT_H + H_DIM, out + OUT_C + H_DIM);
    }
    __threadfence();
    __syncthreads();
    if (threadIdx.x == 0) {
        atomicAdd(&g_c2, 1u);
        spin_geq(&g_c2, (run + 1) * NCHAIN);
    }
    __syncthreads();
    __threadfence();

    // heads
    if (blockIdx.x < 2) {
        int j = blockIdx.x * NTHREADS + threadIdx.x;
        float a0 = 0.f, a1 = 0.f, a2 = 0.f, a3 = 0.f;
#pragma unroll 4
        for (int h = 0; h < H_DIM; h += 4) {
            a0 = fmaf(g_h2[h + 0], Wo[(h + 0) * H_DIM + j], a0);
            a1 = fmaf(g_h2[h + 1], Wo[(h + 1) * H_DIM + j], a1);
            a2 = fmaf(g_h2[h + 2], Wo[(h + 2) * H_DIM + j], a2);
            a3 = fmaf(g_h2[h + 3], Wo[(h + 3) * H_DIM + j], a3);
        }
        out[OUT_OT + j] = tanhf((a0 + a1) + (a2 + a3) + Bo[j]);
    } else if (blockIdx.x == 2) {
        int j = threadIdx.x;
        if (j < V_DIM) {
            float a0 = 0.f, a1 = 0.f, a2 = 0.f, a3 = 0.f;
#pragma unroll 4
            for (int h = 0; h < H_DIM; h += 4) {
                a0 = fmaf(g_h2[h + 0], Wv[(h + 0) * V_DIM + j], a0);
                a1 = fmaf(g_h2[h + 1], Wv[(h + 1) * V_DIM + j], a1);
                a2 = fmaf(g_h2[h + 2], Wv[(h + 2) * V_DIM + j], a2);
                a3 = fmaf(g_h2[h + 3], Wv[(h + 3) * V_DIM + j], a3);
            }
            float v = tanhf((a0 + a1) + (a2 + a3) + Bv[j]);
            g_vt[j] = v;
            out[OUT_VAL + (size_t)T_DEPTH * V_DIM + j] = v;
        }
    } else if (blockIdx.x == 3) {
        if (warp == 0) {
            float a = 0.f;
            for (int h = lane; h < H_DIM; h += 32) a = fmaf(g_h2[h], Wd[h], a);
            a = warp_sum(a);
            if (lane == 0) g_dt = sigm(a + Bd[0]);
        } else if (warp == 1) {
            float a = 0.f;
            for (int h = lane; h < H_DIM; h += 32) a = fmaf(g_h2[h], Wu[h], a);
            a = warp_sum(a);
            if (lane == 0) g_ut = sigm(a + Bu[0]);
        }
    }
    __threadfence();
    __syncthreads();
    if (threadIdx.x == 0) atomicAdd(&g_c3, 1u);

    if (blockIdx.x != 0) {
        // chain blocks 1..63 join the stealing copy
        val_copy_steal(vsrc, vdst, run, &s_chunk);
        return;
    }

    // block 0 waits: heads done (g_dt/g_ut/g_vt) + stg bulk written
    if (threadIdx.x == 0) {
        spin_geq(&g_c3, (run + 1) * NCHAIN);
        spin_geq(&g_cstg, (run + 1) * NCOPY);
    }
    __syncthreads();
    if (warp != 0) return;
    __threadfence();

    // ---------------- fused pop-scan + read (warp 0 of block 0) ----------------
    float* stg = out + OUT_STG;
    const float dt = g_dt;
    float u = g_ut;
    if (lane == 0) stg[T_DEPTH] = dt;

    float rr = 1.0f;
    float r0 = 0.f, r1 = 0.f, r2 = 0.f, r3 = 0.f, r4 = 0.f;
    {
        float coef = fminf(dt, fmaxf(rr, 0.0f));
        if (coef > 0.0f) {
            r0 = fmaf(coef, g_vt[lane], r0);
            r1 = fmaf(coef, g_vt[lane + 32], r1);
            r2 = fmaf(coef, g_vt[lane + 64], r2);
            r3 = fmaf(coef, g_vt[lane + 96], r3);
            if (lane < 2) r4 = fmaf(coef, g_vt[lane + 128], r4);
        }
        rr -= dt;
    }

    bool popping = (u > 0.0f);
    for (int base = T_DEPTH - 32; base >= 0; base -= 32) {
        if (!popping && rr <= 0.0f) break;
        float sv = prev_stg[base + lane];
#pragma unroll
        for (int k = 31; k >= 0; --k) {
            float s = __shfl_sync(0xffffffffu, sv, k);
            float sn = fmaxf(0.0f, s - fmaxf(u, 0.0f));  // == max(0,s) once u<=0
            if (popping && lane == k) stg[base + k] = sn;
            u -= sn;
            if (u <= 0.0f) popping = false;
            float coef = fminf(sn, fmaxf(rr, 0.0f));
            rr -= sn;
            if (coef > 0.0f) {
                const float* row = prev_Val + (size_t)(base + k) * V_DIM;
                r0 = fmaf(coef, row[lane], r0);
                r1 = fmaf(coef, row[lane + 32], r1);
                r2 = fmaf(coef, row[lane + 64], r2);
                r3 = fmaf(coef, row[lane + 96], r3);
                if (lane < 2) r4 = fmaf(coef, row[lane + 128], r4);
            }
        }
    }
    float* rt = out + OUT_RT;
    rt[lane] = r0;
    rt[lane + 32] = r1;
    rt[lane + 64] = r2;
    rt[lane + 96] = r3;
    if (lane < 2) rt[lane + 128] = r4;
}

extern "C" void kernel_launch(void* const* d_in, const int* in_sizes, int n_in,
                              void* d_out, int out_size)
{
    const float* input     = (const float*)d_in[0];
    const float* prev_Val  = (const float*)d_in[1];
    const float* prev_stg  = (const float*)d_in[2];
    const float* prev_read = (const float*)d_in[3];
    const float* prev_h    = (const float*)d_in[4];
    const float* prev_c    = (const float*)d_in[5];
    const float* W_ih0     = (const float*)d_in[6];
    const float* W_hh0     = (const float*)d_in[7];
    const float* b_ih0     = (const float*)d_in[8];
    const float* b_hh0     = (const float*)d_in[9];
    const float* W_ih1     = (const float*)d_in[10];
    const float* W_hh1     = (const float*)d_in[11];
    const float* b_ih1     = (const float*)d_in[12];
    const float* b_hh1     = (const float*)d_in[13];
    const float* Wd        = (const float*)d_in[14];
    const float* Bd        = (const float*)d_in[15];
    const float* Wu        = (const float*)d_in[16];
    const float* Bu        = (const float*)d_in[17];
    const float* Wv        = (const float*)d_in[18];
    const float* Bv        = (const float*)d_in[19];
    const float* Wo        = (const float*)d_in[20];
    const float* Bo        = (const float*)d_in[21];
    float* out = (float*)d_out;

    fused_controller<<<GRID_SZ, NTHREADS>>>(
        input, prev_Val, prev_stg, prev_read, prev_h, prev_c,
        W_ih0, W_hh0, b_ih0, b_hh0, W_ih1, W_hh1, b_ih1, b_hh1,
        Wd, Bd, Wu, Bu, Wv, Bv, Wo, Bo, out);
}

// round 12
// speedup vs baseline: 1.3131x; 1.3131x over previous
#include <cuda_runtime.h>

#define T_DEPTH 200000
#define V_DIM   130
#define H_DIM   512

// Output layout (floats): ot | Val | stg | rt | h_new | c_new
#define OUT_OT  0
#define OUT_VAL 512
#define OUT_STG 26000642   // 512 + 200001*130
#define OUT_RT  26200643
#define OUT_H   26200773
#define OUT_C   26201797

#define NCHAIN   64
#define NCOPY    528
#define GRID_SZ  (NCHAIN + NCOPY)   // 592 = 148 SMs * 4 blocks
#define NTHREADS 256
#define VAL_F4   6500000            // 200000*130/4

// Block-granular work stealing: chunks of 2048 float4 (32 KB).
#define CHUNK_F4   2048
#define NCHUNKS    3174             // 3173 full + 1 partial (1696 f4)
#define NPARTS     (GRID_SZ - 1)    // every block except block 0 steals
#define TICKETS    (NCHUNKS + NPARTS)

#define NT_COPY  (NCOPY * NTHREADS)

__device__ __align__(16) float g_h1[H_DIM];
__device__ __align__(16) float g_h2[H_DIM];
__device__ __align__(16) float g_vt[V_DIM + 2];
__device__ float g_dt, g_ut;

// Monotonic (never reset) counters — safe across graph replays.
__device__ unsigned int g_entry;
__device__ unsigned int g_c1, g_c2, g_c3, g_cstg;
__device__ unsigned int g_work;

__device__ __forceinline__ void spin_geq(unsigned int* p, unsigned int tgt) {
    volatile unsigned int* vp = (volatile unsigned int*)p;
    while (*vp < tgt) __nanosleep(64);
}

__device__ __forceinline__ void l2_prefetch(const void* p) {
    asm volatile("prefetch.global.L2 [%0];" :: "l"(p));
}

__device__ __forceinline__ float warp_sum(float v) {
#pragma unroll
    for (int o = 16; o; o >>= 1) v += __shfl_xor_sync(0xffffffffu, v, o);
    return v;
}
__device__ __forceinline__ float sigm(float x) { return 1.0f / (1.0f + expf(-x)); }

// Block-granular stealing copy over [0, VAL_F4) float4, streaming ld/st.
// Parity double-buffered ticket slot: ONE __syncthreads per chunk.
// Grabs per block per run == chunks_done + 1 (deterministic; total == TICKETS).
__device__ __forceinline__ void val_copy_steal(
    const float4* __restrict__ src, float4* __restrict__ dst,
    unsigned int run, unsigned int* s_slot /* [2] */)
{
    const unsigned int base = run * (unsigned int)TICKETS;
    int p = 0;
    for (;;) {
        if (threadIdx.x == 0) s_slot[p] = atomicAdd(&g_work, 1u) - base;
        __syncthreads();
        unsigned int chunk = s_slot[p];
        p ^= 1;                      // next grab uses the other slot
        if (chunk >= NCHUNKS) break;
        int b = chunk * CHUNK_F4;
        if (chunk != NCHUNKS - 1) {
            int i = b + threadIdx.x;
            float4 v0 = __ldcs(src + i);
            float4 v1 = __ldcs(src + i + 256);
            float4 v2 = __ldcs(src + i + 512);
            float4 v3 = __ldcs(src + i + 768);
            float4 v4 = __ldcs(src + i + 1024);
            float4 v5 = __ldcs(src + i + 1280);
            float4 v6 = __ldcs(src + i + 1536);
            float4 v7 = __ldcs(src + i + 1792);
            __stcs(dst + i, v0);
            __stcs(dst + i + 256, v1);
            __stcs(dst + i + 512, v2);
            __stcs(dst + i + 768, v3);
            __stcs(dst + i + 1024, v4);
            __stcs(dst + i + 1280, v5);
            __stcs(dst + i + 1536, v6);
            __stcs(dst + i + 1792, v7);
        } else {
            for (int j = b + threadIdx.x; j < VAL_F4; j += NTHREADS)
                __stcs(dst + j, __ldcs(src + j));
        }
    }
}

// One warp computes one hidden unit j (all 4 gates) of an LSTM cell.
__device__ __forceinline__ void lstm_cell_warp(
    int j, int lane,
    const float* __restrict__ Wih, const float* __restrict__ Whh,
    const float* __restrict__ bih, const float* __restrict__ bhh,
    const float* __restrict__ x, const float* __restrict__ x2, int in_dim,
    const float* __restrict__ h, const float* __restrict__ c,
    float* __restrict__ hg,
    float* __restrict__ ho, float* __restrict__ co)
{
    float gate[4];
#pragma unroll
    for (int g = 0; g < 4; ++g) {
        int row = g * H_DIM + j;
        const float* wi = Wih + (size_t)row * in_dim;
        float acc = 0.0f;
        for (int k = lane; k < in_dim; k += 32) {
            float xv = x[k];
            if (x2) xv += x2[k];
            acc = fmaf(wi[k], xv, acc);
        }
        const float4* wh4 = reinterpret_cast<const float4*>(Whh + (size_t)row * H_DIM);
        const float4* h4  = reinterpret_cast<const float4*>(h);
#pragma unroll
        for (int m = 0; m < 4; ++m) {
            float4 a = wh4[lane + 32 * m];
            float4 b = h4[lane + 32 * m];
            acc = fmaf(a.x, b.x, acc);
            acc = fmaf(a.y, b.y, acc);
            acc = fmaf(a.z, b.z, acc);
            acc = fmaf(a.w, b.w, acc);
        }
        acc = warp_sum(acc);
        gate[g] = acc + bih[row] + bhh[row];
    }
    if (lane == 0) {
        float ig = sigm(gate[0]);
        float fg = sigm(gate[1]);
        float gg = tanhf(gate[2]);
        float og = sigm(gate[3]);
        float cn = fg * c[j] + ig * gg;
        float hn = og * tanhf(cn);
        hg[j] = hn;              // device-global for next stage
        ho[j] = hn; co[j] = cn;  // output buffer
    }
}

__global__ __launch_bounds__(NTHREADS, 4) void fused_controller(
    const float* __restrict__ input, const float* __restrict__ prev_Val,
    const float* __restrict__ prev_stg, const float* __restrict__ prev_read,
    const float* __restrict__ prev_h, const float* __restrict__ prev_c,
    const float* __restrict__ Wih0, const float* __restrict__ Whh0,
    const float* __restrict__ bih0, const float* __restrict__ bhh0,
    const float* __restrict__ Wih1, const float* __restrict__ Whh1,
    const float* __restrict__ bih1, const float* __restrict__ bhh1,
    const float* __restrict__ Wd, const float* __restrict__ Bd,
    const float* __restrict__ Wu, const float* __restrict__ Bu,
    const float* __restrict__ Wv, const float* __restrict__ Bv,
    const float* __restrict__ Wo, const float* __restrict__ Bo,
    float* __restrict__ out)
{
    __shared__ unsigned int s_run, s_slot[2];
    if (threadIdx.x == 0) {
        unsigned int t = atomicAdd(&g_entry, 1u);
        s_run = t / GRID_SZ;   // all blocks of one launch agree
    }
    __syncthreads();
    const unsigned int run = s_run;

    const float4* vsrc = reinterpret_cast<const float4*>(prev_Val);
    float4* vdst = reinterpret_cast<float4*>(out + OUT_VAL);
    const int warp = threadIdx.x >> 5;
    const int lane = threadIdx.x & 31;

    // ---------------- COPY ROLE (blocks NCHAIN..) ----------------
    if (blockIdx.x >= NCHAIN) {
        const int tid = (blockIdx.x - NCHAIN) * NTHREADS + threadIdx.x;

        // L2 prefetch of weights used by the chain (128B lines).
        {
            const char* p;
            p = (const char*)Wih0; for (int l = tid; l < 8320;  l += NT_COPY) l2_prefetch(p + (size_t)l * 128);
            p = (const char*)Whh0; for (int l = tid; l < 32768; l += NT_COPY) l2_prefetch(p + (size_t)l * 128);
            p = (const char*)Wih1; for (int l = tid; l < 32768; l += NT_COPY) l2_prefetch(p + (size_t)l * 128);
            p = (const char*)Whh1; for (int l = tid; l < 32768; l += NT_COPY) l2_prefetch(p + (size_t)l * 128);
            p = (const char*)Wo;   for (int l = tid; l < 8192;  l += NT_COPY) l2_prefetch(p + (size_t)l * 128);
            p = (const char*)Wv;   for (int l = tid; l < 2080;  l += NT_COPY) l2_prefetch(p + (size_t)l * 128);
        }

        // stg bulk: stg[i] = max(0, prev_stg[i]); the scan overwrites the
        // popped prefix later (ordered via g_cstg).
        const float2* s2 = reinterpret_cast<const float2*>(prev_stg);
        float2* d2 = reinterpret_cast<float2*>(out + OUT_STG);
        for (int i = tid; i < T_DEPTH / 2; i += NT_COPY) {
            float2 v = s2[i];
            v.x = fmaxf(v.x, 0.0f);
            v.y = fmaxf(v.y, 0.0f);
            d2[i] = v;
        }
        __threadfence();
        __syncthreads();
        if (threadIdx.x == 0) atomicAdd(&g_cstg, 1u);

        val_copy_steal(vsrc, vdst, run, s_slot);
        return;
    }

    // ---------------- CHAIN ROLE (blocks 0..63) ----------------

    // cell0: 8 warps/block x 64 blocks = 512 units
    {
        int j = blockIdx.x * 8 + warp;
        lstm_cell_warp(j, lane, Wih0, Whh0, bih0, bhh0,
                       input, prev_read, V_DIM,
                       prev_h, prev_c,
                       g_h1, out + OUT_H, out + OUT_C);
    }
    __threadfence();
    __syncthreads();
    if (threadIdx.x == 0) {
        atomicAdd(&g_c1, 1u);
        spin_geq(&g_c1, (run + 1) * NCHAIN);
    }
    __syncthreads();
    __threadfence();

    // cell1
    {
        int j = blockIdx.x * 8 + warp;
        lstm_cell_warp(j, lane, Wih1, Whh1, bih1, bhh1,
                       g_h1, nullptr, H_DIM,
                       prev_h + H_DIM, prev_c + H_DIM,
                       g_h2, out + OUT_H + H_DIM, out + OUT_C + H_DIM);
    }
    __threadfence();
    __syncthreads();
    if (threadIdx.x == 0) {
        atomicAdd(&g_c2, 1u);
        spin_geq(&g_c2, (run + 1) * NCHAIN);
    }
    __syncthreads();
    __threadfence();

    // heads
    if (blockIdx.x < 2) {
        int j = blockIdx.x * NTHREADS + threadIdx.x;
        float a0 = 0.f, a1 = 0.f, a2 = 0.f, a3 = 0.f;
#pragma unroll 4
        for (int h = 0; h < H_DIM; h += 4) {
            a0 = fmaf(g_h2[h + 0], Wo[(h + 0) * H_DIM + j], a0);
            a1 = fmaf(g_h2[h + 1], Wo[(h + 1) * H_DIM + j], a1);
            a2 = fmaf(g_h2[h + 2], Wo[(h + 2) * H_DIM + j], a2);
            a3 = fmaf(g_h2[h + 3], Wo[(h + 3) * H_DIM + j], a3);
        }
        out[OUT_OT + j] = tanhf((a0 + a1) + (a2 + a3) + Bo[j]);
    } else if (blockIdx.x == 2) {
        int j = threadIdx.x;
        if (j < V_DIM) {
            float a0 = 0.f, a1 = 0.f, a2 = 0.f, a3 = 0.f;
#pragma unroll 4
            for (int h = 0; h < H_DIM; h += 4) {
                a0 = fmaf(g_h2[h + 0], Wv[(h + 0) * V_DIM + j], a0);
                a1 = fmaf(g_h2[h + 1], Wv[(h + 1) * V_DIM + j], a1);
                a2 = fmaf(g_h2[h + 2], Wv[(h + 2) * V_DIM + j], a2);
                a3 = fmaf(g_h2[h + 3], Wv[(h + 3) * V_DIM + j], a3);
            }
            float v = tanhf((a0 + a1) + (a2 + a3) + Bv[j]);
            g_vt[j] = v;
            out[OUT_VAL + (size_t)T_DEPTH * V_DIM + j] = v;
        }
    } else if (blockIdx.x == 3) {
        if (warp == 0) {
            float a = 0.f;
            for (int h = lane; h < H_DIM; h += 32) a = fmaf(g_h2[h], Wd[h], a);
            a = warp_sum(a);
            if (lane == 0) g_dt = sigm(a + Bd[0]);
        } else if (warp == 1) {
            float a = 0.f;
            for (int h = lane; h < H_DIM; h += 32) a = fmaf(g_h2[h], Wu[h], a);
            a = warp_sum(a);
            if (lane == 0) g_ut = sigm(a + Bu[0]);
        }
    }
    __threadfence();
    __syncthreads();
    if (threadIdx.x == 0) atomicAdd(&g_c3, 1u);

    if (blockIdx.x != 0) {
        // chain blocks 1..63 join the stealing copy
        val_copy_steal(vsrc, vdst, run, s_slot);
        return;
    }

    // block 0 waits: heads done (g_dt/g_ut/g_vt) + stg bulk written
    if (threadIdx.x == 0) {
        spin_geq(&g_c3, (run + 1) * NCHAIN);
        spin_geq(&g_cstg, (run + 1) * NCOPY);
    }
    __syncthreads();
    if (warp != 0) return;
    __threadfence();

    // ---------------- fused pop-scan + read (warp 0 of block 0) ----------------
    float* stg = out + OUT_STG;
    const float dt = g_dt;
    float u = g_ut;
    if (lane == 0) stg[T_DEPTH] = dt;

    float rr = 1.0f;
    float r0 = 0.f, r1 = 0.f, r2 = 0.f, r3 = 0.f, r4 = 0.f;
    {
        float coef = fminf(dt, fmaxf(rr, 0.0f));
        if (coef > 0.0f) {
            r0 = fmaf(coef, g_vt[lane], r0);
            r1 = fmaf(coef, g_vt[lane + 32], r1);
            r2 = fmaf(coef, g_vt[lane + 64], r2);
            r3 = fmaf(coef, g_vt[lane + 96], r3);
            if (lane < 2) r4 = fmaf(coef, g_vt[lane + 128], r4);
        }
        rr -= dt;
    }

    bool popping = (u > 0.0f);
    for (int base = T_DEPTH - 32; base >= 0; base -= 32) {
        if (!popping && rr <= 0.0f) break;
        float sv = prev_stg[base + lane];
#pragma unroll
        for (int k = 31; k >= 0; --k) {
            float s = __shfl_sync(0xffffffffu, sv, k);
            float sn = fmaxf(0.0f, s - fmaxf(u, 0.0f));  // == max(0,s) once u<=0
            if (popping && lane == k) stg[base + k] = sn;
            u -= sn;
            if (u <= 0.0f) popping = false;
            float coef = fminf(sn, fmaxf(rr, 0.0f));
            rr -= sn;
            if (coef > 0.0f) {
                const float* row = prev_Val + (size_t)(base + k) * V_DIM;
                r0 = fmaf(coef, row[lane], r0);
                r1 = fmaf(coef, row[lane + 32], r1);
                r2 = fmaf(coef, row[lane + 64], r2);
                r3 = fmaf(coef, row[lane + 96], r3);
                if (lane < 2) r4 = fmaf(coef, row[lane + 128], r4);
            }
        }
    }
    float* rt = out + OUT_RT;
    rt[lane] = r0;
    rt[lane + 32] = r1;
    rt[lane + 64] = r2;
    rt[lane + 96] = r3;
    if (lane < 2) rt[lane + 128] = r4;
}

extern "C" void kernel_launch(void* const* d_in, const int* in_sizes, int n_in,
                              void* d_out, int out_size)
{
    const float* input     = (const float*)d_in[0];
    const float* prev_Val  = (const float*)d_in[1];
    const float* prev_stg  = (const float*)d_in[2];
    const float* prev_read = (const float*)d_in[3];
    const float* prev_h    = (const float*)d_in[4];
    const float* prev_c    = (const float*)d_in[5];
    const float* W_ih0     = (const float*)d_in[6];
    const float* W_hh0     = (const float*)d_in[7];
    const float* b_ih0     = (const float*)d_in[8];
    const float* b_hh0     = (const float*)d_in[9];
    const float* W_ih1     = (const float*)d_in[10];
    const float* W_hh1     = (const float*)d_in[11];
    const float* b_ih1     = (const float*)d_in[12];
    const float* b_hh1     = (const float*)d_in[13];
    const float* Wd        = (const float*)d_in[14];
    const float* Bd        = (const float*)d_in[15];
    const float* Wu        = (const float*)d_in[16];
    const float* Bu        = (const float*)d_in[17];
    const float* Wv        = (const float*)d_in[18];
    const float* Bv        = (const float*)d_in[19];
    const float* Wo        = (const float*)d_in[20];
    const float* Bo        = (const float*)d_in[21];
    float* out = (float*)d_out;

    fused_controller<<<GRID_SZ, NTHREADS>>>(
        input, prev_Val, prev_stg, prev_read, prev_h, prev_c,
        W_ih0, W_hh0, b_ih0, b_hh0, W_ih1, W_hh1, b_ih1, b_hh1,
        Wd, Bd, Wu, Bu, Wv, Bv, Wo, Bo, out);
}